// round 15
// baseline (speedup 1.0000x reference)
#include <cuda_runtime.h>
#include <cstdint>

// LSTM: B=2048, T=4096, I=5, H=10. Gate order i,f,g,o (rows of W_ih/W_hh).
//   gates = x @ W_ih^T + b_ih + b_hh + h @ W_hh^T
//   c = sigmoid(f)*c + sigmoid(i)*tanh(g);  h = sigmoid(o)*tanh(c)
//
// R14 = R13 math with fixed launch geometry.
//   KEY FIX: warps map to SMSPs by (wid % 4) WITHIN a CTA. 32-thread blocks
//   put every warp on SMSP 0, stacking 2-5 warps on one scheduler while
//   SMSPs 1-3 idle (this capped R3-R13 at ~1.2ms). Now: 128-thread blocks,
//   4 independent warps each -> 86 blocks <= 148 SMs -> exactly 1 warp per
//   active SMSP, zero scheduler contention.
//   Per warp: 6 batches, 5 lanes/batch, 2 hidden units per lane.
//   - h exchange: 5x u64 shuffles carrying natural K-pairs (h_{2k},h_{2k+1}),
//     interleaved with recurrent FFMA2 batches.
//   - K-pair f32x2 accumulation, one horizontal FADD per gate row.
//   - guarded STG.64 output store (two adjacent units).
//   - x prefetch distance 2 steps.
//   - MUFU.TANH activations; sigmoid(x)=0.5+0.5*tanh(x/2) with the 0.5
//     folded into pre-scaled weights/biases.

#define BB 2048
#define TT 4096
#define II 5
#define HH 10

typedef unsigned long long u64;

static __device__ __forceinline__ u64 pk2(float a, float b) {
    u64 r;
    asm("mov.b64 %0, {%1, %2};" : "=l"(r) : "f"(a), "f"(b));
    return r;
}
static __device__ __forceinline__ void upk2(u64 v, float& a, float& b) {
    asm("mov.b64 {%0, %1}, %2;" : "=f"(a), "=f"(b) : "l"(v));
}
static __device__ __forceinline__ u64 ffma2(u64 a, u64 b, u64 c) {
    u64 d;
    asm("fma.rn.f32x2 %0, %1, %2, %3;" : "=l"(d) : "l"(a), "l"(b), "l"(c));
    return d;
}
// Single-MUFU tanh (MUFU.TANH), sm_75+.
static __device__ __forceinline__ float tanh_x(float x) {
    float y;
    asm("tanh.approx.f32 %0, %1;" : "=f"(y) : "f"(x));
    return y;
}
static __device__ __forceinline__ u64 shfl64(u64 v, int src) {
    return __shfl_sync(0xFFFFFFFFu, v, src);
}

__global__ void __launch_bounds__(128)
lstm_scan_kernel(const float* __restrict__ x,
                 const float* __restrict__ h0,
                 const float* __restrict__ c0,
                 const float* __restrict__ W_ih,
                 const float* __restrict__ W_hh,
                 const float* __restrict__ b_ih,
                 const float* __restrict__ b_hh,
                 float* __restrict__ out)
{
    const int wid   = threadIdx.x >> 5;   // warp within block -> SMSP wid%4
    const int lane  = threadIdx.x & 31;
    const int group = (lane < 30) ? (lane / 5) : 0;
    const int m     = (lane < 30) ? (lane - group * 5) : 0;
    const int g5    = group * 5;

    int b = blockIdx.x * 24 + wid * 6 + group;
    const bool active = (lane < 30) && (b < BB);
    if (b >= BB) b = 0;  // clamp for safe (redundant) loads; store is guarded

    const int u0 = 2 * m, u1 = 2 * m + 1;

    // 8 gate rows: [f,i,g,o] for unit0 then unit1. f first per unit (it heads
    // the c -> tanh(c) -> h chain). Sigmoid rows pre-scaled by 0.5.
    const int rows[8] = {HH + u0, u0, 2 * HH + u0, 3 * HH + u0,
                         HH + u1, u1, 2 * HH + u1, 3 * HH + u1};
    const float scs[8] = {0.5f, 0.5f, 1.0f, 0.5f, 0.5f, 0.5f, 1.0f, 0.5f};

    u64 whh2[8][5], wih2[8][2];
    float w4[8], bias[8];
#pragma unroll
    for (int r = 0; r < 8; r++) {
        const int row = rows[r];
        const float s = scs[r];
#pragma unroll
        for (int k = 0; k < 5; k++)
            whh2[r][k] = pk2(s * W_hh[row * HH + 2 * k],
                             s * W_hh[row * HH + 2 * k + 1]);
        wih2[r][0] = pk2(s * W_ih[row * II + 0], s * W_ih[row * II + 1]);
        wih2[r][1] = pk2(s * W_ih[row * II + 2], s * W_ih[row * II + 3]);
        w4[r]   = s * W_ih[row * II + 4];
        bias[r] = s * (b_ih[row] + b_hh[row]);
    }

    float hA = h0[b * HH + u0], hB = h0[b * HH + u1];
    float cA = c0[b * HH + u0], cB = c0[b * HH + u1];
    u64 hpk = pk2(hA, hB);  // this lane's published K-pair

    const float* xbase = x + (size_t)b * TT * II;
    float* ob = out + ((size_t)b * TT * HH + u0);

    // x prefetch ring, distance 2.
    float xA0 = xbase[0], xA1 = xbase[1], xA2 = xbase[2],
          xA3 = xbase[3], xA4 = xbase[4];
    float xB0 = xbase[II + 0], xB1 = xbase[II + 1], xB2 = xbase[II + 2],
          xB3 = xbase[II + 3], xB4 = xbase[II + 4];

#pragma unroll 1
    for (int t = 0; t < TT; ++t) {
        const float xc0 = xA0, xc1 = xA1, xc2 = xA2, xc3 = xA3, xc4 = xA4;

        // Shift ring and prefetch t+2 (independent of the recurrent chain).
        {
            const int tn = (t + 2 < TT) ? (t + 2) : (TT - 1);
            const float* xp = xbase + (size_t)tn * II;
            xA0 = xB0; xA1 = xB1; xA2 = xB2; xA3 = xB3; xA4 = xB4;
            xB0 = xp[0]; xB1 = xp[1]; xB2 = xp[2]; xB3 = xp[3]; xB4 = xp[4];
        }

        // First h K-pair shuffle in flight while x contribution computes.
        u64 p0 = shfl64(hpk, g5 + 0);

        const u64 xp01 = pk2(xc0, xc1);
        const u64 xp23 = pk2(xc2, xc3);
        u64 acc[8];
#pragma unroll
        for (int r = 0; r < 8; r++)
            acc[r] = pk2(fmaf(w4[r], xc4, bias[r]), 0.0f);
#pragma unroll
        for (int r = 0; r < 8; r++) acc[r] = ffma2(wih2[r][0], xp01, acc[r]);
#pragma unroll
        for (int r = 0; r < 8; r++) acc[r] = ffma2(wih2[r][1], xp23, acc[r]);

        // Pipelined: shuffle k+1 while consuming pair k.
        u64 p1 = shfl64(hpk, g5 + 1);
#pragma unroll
        for (int r = 0; r < 8; r++) acc[r] = ffma2(whh2[r][0], p0, acc[r]);
        u64 p2 = shfl64(hpk, g5 + 2);
#pragma unroll
        for (int r = 0; r < 8; r++) acc[r] = ffma2(whh2[r][1], p1, acc[r]);
        u64 p3 = shfl64(hpk, g5 + 3);
#pragma unroll
        for (int r = 0; r < 8; r++) acc[r] = ffma2(whh2[r][2], p2, acc[r]);
        u64 p4 = shfl64(hpk, g5 + 4);
#pragma unroll
        for (int r = 0; r < 8; r++) acc[r] = ffma2(whh2[r][3], p3, acc[r]);
#pragma unroll
        for (int r = 0; r < 8; r++) acc[r] = ffma2(whh2[r][4], p4, acc[r]);

        // Horizontal adds -> scalar gate args.
        float a[8];
#pragma unroll
        for (int r = 0; r < 8; r++) {
            float lo, hi;
            upk2(acc[r], lo, hi);
            a[r] = lo + hi;
        }

        // Unit 0.
        const float fg0 = fmaf(0.5f, tanh_x(a[0]), 0.5f);
        const float ig0 = fmaf(0.5f, tanh_x(a[1]), 0.5f);
        const float gg0 = tanh_x(a[2]);
        const float og0 = fmaf(0.5f, tanh_x(a[3]), 0.5f);
        cA = fmaf(fg0, cA, ig0 * gg0);
        hA = og0 * tanh_x(cA);

        // Unit 1 (independent tail; overlaps unit 0's MUFU latency).
        const float fg1 = fmaf(0.5f, tanh_x(a[4]), 0.5f);
        const float ig1 = fmaf(0.5f, tanh_x(a[5]), 0.5f);
        const float gg1 = tanh_x(a[6]);
        const float og1 = fmaf(0.5f, tanh_x(a[7]), 0.5f);
        cB = fmaf(fg1, cB, ig1 * gg1);
        hB = og1 * tanh_x(cB);

        hpk = pk2(hA, hB);

        if (active) {
            float2 hv = make_float2(hA, hB);
            *(float2*)(ob + (size_t)t * HH) = hv;  // 8B-aligned (u0 even)
        }
    }
}

extern "C" void kernel_launch(void* const* d_in, const int* in_sizes, int n_in,
                              void* d_out, int out_size) {
    (void)in_sizes; (void)n_in; (void)out_size;
    const float* x    = (const float*)d_in[0];
    const float* h0   = (const float*)d_in[1];
    const float* c0   = (const float*)d_in[2];
    const float* W_ih = (const float*)d_in[3];
    const float* W_hh = (const float*)d_in[4];
    const float* b_ih = (const float*)d_in[5];
    const float* b_hh = (const float*)d_in[6];
    float* out = (float*)d_out;

    // 24 batches per 128-thread block (4 warps x 6 batches).
    const int nblocks = (BB + 23) / 24;  // 86 blocks <= 148 SMs
    lstm_scan_kernel<<<nblocks, 128>>>(x, h0, c0, W_ih, W_hh, b_ih, b_hh, out);
}

// round 16
// speedup vs baseline: 2.0330x; 2.0330x over previous
#include <cuda_runtime.h>
#include <cstdint>

// LSTM: B=2048, T=4096, I=5, H=10. Gate order i,f,g,o (rows of W_ih/W_hh).
//   gates = x @ W_ih^T + b_ih + b_hh + h @ W_hh^T
//   c = sigmoid(f)*c + sigmoid(i)*tanh(g);  h = sigmoid(o)*tanh(c)
//
// R16 = R7 (best: 1182us) + issue-slot trims:
//   - manual unroll x2: two x register sets (even/odd t), each reloaded
//     AFTER consumption -> no ring-copy MOVs, halved loop overhead, and
//     ~2-step effective prefetch distance (covers DRAM miss on the x line).
//   - everything else byte-identical to R7: interleaved shuffles (hoisting
//     measured worse), gate-pair f32x2 FMA, guarded store (sink measured
//     catastrophically worse), MUFU.TANH with sigmoid(x)=0.5+0.5*tanh(x/2)
//     folded into pre-scaled weights.

#define BB 2048
#define TT 4096
#define II 5
#define HH 10

typedef unsigned long long u64;

static __device__ __forceinline__ u64 pk2(float a, float b) {
    u64 r;
    asm("mov.b64 %0, {%1, %2};" : "=l"(r) : "f"(a), "f"(b));
    return r;
}
static __device__ __forceinline__ void upk2(u64 v, float& a, float& b) {
    asm("mov.b64 {%0, %1}, %2;" : "=f"(a), "=f"(b) : "l"(v));
}
static __device__ __forceinline__ u64 ffma2(u64 a, u64 b, u64 c) {
    u64 d;
    asm("fma.rn.f32x2 %0, %1, %2, %3;" : "=l"(d) : "l"(a), "l"(b), "l"(c));
    return d;
}
static __device__ __forceinline__ u64 fadd2(u64 a, u64 b) {
    u64 d;
    asm("add.rn.f32x2 %0, %1, %2;" : "=l"(d) : "l"(a), "l"(b));
    return d;
}
// Single-MUFU tanh (MUFU.TANH), sm_75+.
static __device__ __forceinline__ float tanh_x(float x) {
    float y;
    asm("tanh.approx.f32 %0, %1;" : "=f"(y) : "f"(x));
    return y;
}

__global__ void __launch_bounds__(32)
lstm_scan_kernel(const float* __restrict__ x,
                 const float* __restrict__ h0,
                 const float* __restrict__ c0,
                 const float* __restrict__ W_ih,
                 const float* __restrict__ W_hh,
                 const float* __restrict__ b_ih,
                 const float* __restrict__ b_hh,
                 float* __restrict__ out)
{
    const int lane = threadIdx.x;
    const int group = (lane < 30) ? (lane / 10) : 0;
    const int j     = (lane < 30) ? (lane - group * 10) : 0;
    const int gbase = group * 10;

    int b = blockIdx.x * 3 + group;
    const bool active = (lane < 30) && (b < BB);
    if (b >= BB) b = 0;  // clamp for safe (redundant) loads; store is guarded

    // Gate rows for this hidden unit.
    const int ri = j, rf = HH + j, rg = 2 * HH + j, ro = 3 * HH + j;

    // Register-resident packed weights. Sigmoid gates (i,f,o) pre-scaled by
    // 0.5 so sigmoid(x) = 0.5 + 0.5*tanh(acc).
    u64 wih_if[II], wih_go[II], whh_if[HH], whh_go[HH];
#pragma unroll
    for (int i = 0; i < II; i++) {
        wih_if[i] = pk2(0.5f * W_ih[ri * II + i], 0.5f * W_ih[rf * II + i]);
        wih_go[i] = pk2(       W_ih[rg * II + i], 0.5f * W_ih[ro * II + i]);
    }
#pragma unroll
    for (int k = 0; k < HH; k++) {
        whh_if[k] = pk2(0.5f * W_hh[ri * HH + k], 0.5f * W_hh[rf * HH + k]);
        whh_go[k] = pk2(       W_hh[rg * HH + k], 0.5f * W_hh[ro * HH + k]);
    }
    const u64 bias_if = pk2(0.5f * (b_ih[ri] + b_hh[ri]),
                            0.5f * (b_ih[rf] + b_hh[rf]));
    const u64 bias_go = pk2(        b_ih[rg] + b_hh[rg],
                            0.5f * (b_ih[ro] + b_hh[ro]));

    float h = h0[b * HH + j];
    float c = c0[b * HH + j];

    const float* xb = x + (size_t)b * TT * II;
    float* ob = out + (size_t)b * TT * HH + j;

    // Two x register sets: xa = even t, xbr = odd t. Preload t=0 and t=1.
    float xa[II], xbr[II];
#pragma unroll
    for (int i = 0; i < II; i++) xa[i]  = xb[i];
#pragma unroll
    for (int i = 0; i < II; i++) xbr[i] = xb[II + i];

    // One LSTM step: consumes xc[], updates h, c, stores h at time t.
    // (Lambda-free macro to guarantee identical codegen in both halves.)
#define LSTM_STEP(XC, T)                                                      \
    do {                                                                      \
        const float hk0 = __shfl_sync(0xFFFFFFFFu, h, gbase + 0);             \
        u64 aif0 = bias_if, aif1 = 0ull;                                      \
        u64 ago0 = bias_go, ago1 = 0ull;                                      \
        _Pragma("unroll")                                                     \
        for (int i = 0; i < II; i++) {                                        \
            u64 xx = pk2((XC)[i], (XC)[i]);                                   \
            if (i & 1) {                                                      \
                aif1 = ffma2(wih_if[i], xx, aif1);                            \
                ago1 = ffma2(wih_go[i], xx, ago1);                            \
            } else {                                                          \
                aif0 = ffma2(wih_if[i], xx, aif0);                            \
                ago0 = ffma2(wih_go[i], xx, ago0);                            \
            }                                                                 \
        }                                                                     \
        {                                                                     \
            u64 hh;                                                           \
            const float hk1 = __shfl_sync(0xFFFFFFFFu, h, gbase + 1);         \
            hh = pk2(hk0, hk0);                                               \
            aif0 = ffma2(whh_if[0], hh, aif0);                                \
            ago0 = ffma2(whh_go[0], hh, ago0);                                \
            const float hk2 = __shfl_sync(0xFFFFFFFFu, h, gbase + 2);         \
            hh = pk2(hk1, hk1);                                               \
            aif1 = ffma2(whh_if[1], hh, aif1);                                \
            ago1 = ffma2(whh_go[1], hh, ago1);                                \
            const float hk3 = __shfl_sync(0xFFFFFFFFu, h, gbase + 3);         \
            hh = pk2(hk2, hk2);                                               \
            aif0 = ffma2(whh_if[2], hh, aif0);                                \
            ago0 = ffma2(whh_go[2], hh, ago0);                                \
            const float hk4 = __shfl_sync(0xFFFFFFFFu, h, gbase + 4);         \
            hh = pk2(hk3, hk3);                                               \
            aif1 = ffma2(whh_if[3], hh, aif1);                                \
            ago1 = ffma2(whh_go[3], hh, ago1);                                \
            const float hk5 = __shfl_sync(0xFFFFFFFFu, h, gbase + 5);         \
            hh = pk2(hk4, hk4);                                               \
            aif0 = ffma2(whh_if[4], hh, aif0);                                \
            ago0 = ffma2(whh_go[4], hh, ago0);                                \
            const float hk6 = __shfl_sync(0xFFFFFFFFu, h, gbase + 6);         \
            hh = pk2(hk5, hk5);                                               \
            aif1 = ffma2(whh_if[5], hh, aif1);                                \
            ago1 = ffma2(whh_go[5], hh, ago1);                                \
            const float hk7 = __shfl_sync(0xFFFFFFFFu, h, gbase + 7);         \
            hh = pk2(hk6, hk6);                                               \
            aif0 = ffma2(whh_if[6], hh, aif0);                                \
            ago0 = ffma2(whh_go[6], hh, ago0);                                \
            const float hk8 = __shfl_sync(0xFFFFFFFFu, h, gbase + 8);         \
            hh = pk2(hk7, hk7);                                               \
            aif1 = ffma2(whh_if[7], hh, aif1);                                \
            ago1 = ffma2(whh_go[7], hh, ago1);                                \
            const float hk9 = __shfl_sync(0xFFFFFFFFu, h, gbase + 9);         \
            hh = pk2(hk8, hk8);                                               \
            aif0 = ffma2(whh_if[8], hh, aif0);                                \
            ago0 = ffma2(whh_go[8], hh, ago0);                                \
            hh = pk2(hk9, hk9);                                               \
            aif1 = ffma2(whh_if[9], hh, aif1);                                \
            ago1 = ffma2(whh_go[9], hh, ago1);                                \
        }                                                                     \
        u64 aif = fadd2(aif0, aif1);                                          \
        u64 ago = fadd2(ago0, ago1);                                          \
        float ai, af, ag, ao;                                                 \
        upk2(aif, ai, af);                                                    \
        upk2(ago, ag, ao);                                                    \
        const float fg = fmaf(0.5f, tanh_x(af), 0.5f);                        \
        const float ig = fmaf(0.5f, tanh_x(ai), 0.5f);                        \
        const float gg = tanh_x(ag);                                          \
        const float og = fmaf(0.5f, tanh_x(ao), 0.5f);                        \
        c = fmaf(fg, c, ig * gg);                                             \
        h = og * tanh_x(c);                                                   \
        if (active) ob[(size_t)(T) * HH] = h;                                 \
    } while (0)

#pragma unroll 1
    for (int t = 0; t < TT; t += 2) {
        // Even step: consume xa, then reload xa for t+2 (issues ~1 full step
        // before its consumption -> DRAM latency fully covered).
        LSTM_STEP(xa, t);
        {
            const int tn = (t + 2 < TT) ? (t + 2) : (TT - 1);
            const float* xp = xb + (size_t)tn * II;
#pragma unroll
            for (int i = 0; i < II; i++) xa[i] = xp[i];
        }

        // Odd step: consume xbr, then reload xbr for t+3.
        LSTM_STEP(xbr, t + 1);
        {
            const int tn = (t + 3 < TT) ? (t + 3) : (TT - 1);
            const float* xp = xb + (size_t)tn * II;
#pragma unroll
            for (int i = 0; i < II; i++) xbr[i] = xp[i];
        }
    }
#undef LSTM_STEP
}

extern "C" void kernel_launch(void* const* d_in, const int* in_sizes, int n_in,
                              void* d_out, int out_size) {
    (void)in_sizes; (void)n_in; (void)out_size;
    const float* x    = (const float*)d_in[0];
    const float* h0   = (const float*)d_in[1];
    const float* c0   = (const float*)d_in[2];
    const float* W_ih = (const float*)d_in[3];
    const float* W_hh = (const float*)d_in[4];
    const float* b_ih = (const float*)d_in[5];
    const float* b_hh = (const float*)d_in[6];
    float* out = (float*)d_out;

    const int nwarps = (BB + 2) / 3;  // 3 batches per warp
    lstm_scan_kernel<<<nwarps, 32>>>(x, h0, c0, W_ih, W_hh, b_ih, b_hh, out);
}